// round 1
// baseline (speedup 1.0000x reference)
#include <cuda_runtime.h>
#include <cuda_bf16.h>

// Output: out[b,c,h,w] = x[b,c, 2h+o, 2w+p], where (o,p)=divmod(i,2).
// B*C = 24 images, in 2048x2048, out 1024x1024.
// Each thread writes one float4 of output (4 consecutive out columns),
// reading two aligned float4 from the source row and selecting lanes by p.

static constexpr int H_IN  = 2048;
static constexpr int W_IN  = 2048;
static constexpr int H_OUT = 1024;
static constexpr int W_OUT = 1024;
static constexpr int W_OUT4 = W_OUT / 4;              // 256 float4 per out row
static constexpr long IMG_IN  = (long)H_IN * W_IN;    // 4,194,304
static constexpr long IMG_OUT4 = (long)H_OUT * W_OUT4; // 262,144 float4 per image

__global__ void __launch_bounds__(256) slice_stride2_kernel(
    const float* __restrict__ x,
    const int* __restrict__ ip,
    float4* __restrict__ out,
    long total4)
{
    long t = (long)blockIdx.x * blockDim.x + threadIdx.x;
    if (t >= total4) return;

    const int iv = ip[0];
    const int o = (iv >> 1) & 1;
    const int p = iv & 1;

    // Decompose t -> (img, out_row, out_col4). W_OUT4=256, H_OUT=1024 are pow2.
    const int  w4  = (int)(t & (W_OUT4 - 1));
    const int  row = (int)((t >> 8) & (H_OUT - 1));
    const long img = t >> 18;

    const float* src = x + img * IMG_IN + (long)(2 * row + o) * W_IN + (long)w4 * 8;
    const float4 a = __ldg((const float4*)(src));
    const float4 b = __ldg((const float4*)(src + 4));

    float4 r;
    if (p == 0) { r.x = a.x; r.y = a.z; r.z = b.x; r.w = b.z; }
    else        { r.x = a.y; r.y = a.w; r.z = b.y; r.w = b.w; }

    out[t] = r;
}

extern "C" void kernel_launch(void* const* d_in, const int* in_sizes, int n_in,
                              void* d_out, int out_size)
{
    const float* x  = (const float*)d_in[0];
    const int*   ip = (const int*)d_in[1];
    float4* out = (float4*)d_out;

    const long total4 = (long)out_size / 4;   // 6,291,456
    const int threads = 256;
    const int blocks = (int)((total4 + threads - 1) / threads);
    slice_stride2_kernel<<<blocks, threads>>>(x, ip, out, total4);
}

// round 2
// speedup vs baseline: 1.0249x; 1.0249x over previous
#include <cuda_runtime.h>
#include <cuda_bf16.h>

// Output: out[b,c,h,w] = x[b,c, 2h+o, 2w+p], where (o,p)=divmod(i,2).
// B*C = 24 images, in 2048x2048, out 1024x1024.
// Each thread writes one float4 of output (4 consecutive out columns),
// reading two aligned float4 from the source row and selecting lanes by p.

static constexpr int H_IN  = 2048;
static constexpr int W_IN  = 2048;
static constexpr int H_OUT = 1024;
static constexpr int W_OUT = 1024;
static constexpr int W_OUT4 = W_OUT / 4;              // 256 float4 per out row
static constexpr long IMG_IN  = (long)H_IN * W_IN;    // 4,194,304
static constexpr long IMG_OUT4 = (long)H_OUT * W_OUT4; // 262,144 float4 per image

__global__ void __launch_bounds__(256) slice_stride2_kernel(
    const float* __restrict__ x,
    const int* __restrict__ ip,
    float4* __restrict__ out,
    long total4)
{
    long t = (long)blockIdx.x * blockDim.x + threadIdx.x;
    if (t >= total4) return;

    const int iv = ip[0];
    const int o = (iv >> 1) & 1;
    const int p = iv & 1;

    // Decompose t -> (img, out_row, out_col4). W_OUT4=256, H_OUT=1024 are pow2.
    const int  w4  = (int)(t & (W_OUT4 - 1));
    const int  row = (int)((t >> 8) & (H_OUT - 1));
    const long img = t >> 18;

    const float* src = x + img * IMG_IN + (long)(2 * row + o) * W_IN + (long)w4 * 8;
    const float4 a = __ldg((const float4*)(src));
    const float4 b = __ldg((const float4*)(src + 4));

    float4 r;
    if (p == 0) { r.x = a.x; r.y = a.z; r.z = b.x; r.w = b.z; }
    else        { r.x = a.y; r.y = a.w; r.z = b.y; r.w = b.w; }

    out[t] = r;
}

extern "C" void kernel_launch(void* const* d_in, const int* in_sizes, int n_in,
                              void* d_out, int out_size)
{
    const float* x  = (const float*)d_in[0];
    const int*   ip = (const int*)d_in[1];
    float4* out = (float4*)d_out;

    const long total4 = (long)out_size / 4;   // 6,291,456
    const int threads = 256;
    const int blocks = (int)((total4 + threads - 1) / threads);
    slice_stride2_kernel<<<blocks, threads>>>(x, ip, out, total4);
}